// round 2
// baseline (speedup 1.0000x reference)
#include <cuda_runtime.h>
#include <cuda_bf16.h>

// Problem constants
#define BSZ   128
#define NN_   32
#define D_    3072
#define H_    1024
#define Z_    32
#define MALL  (BSZ + BSZ*NN_)   // 4224 encoder rows
#define MNB   (BSZ*NN_)         // 4096 neighbor rows

// ---------------- scratch (static device globals; allocation-free) ----------
__device__ float g_H1[MALL * H_];     // encoder layer-1 out (4224,1024)
__device__ float g_H2[MALL * H_];     // encoder layer-2 out
__device__ float g_Zl[MALL * Z_];     // latent (4224,32): rows 0..127 = z_c
__device__ float g_dz[MNB * Z_];      // z_nn - z_c (4096,32)
__device__ float g_h1c[BSZ * H_];     // decoder L1 act at z_c (128,1024)
__device__ float g_s1 [BSZ * H_];     // decoder L1 mask
__device__ float g_h2c[BSZ * H_];     // decoder L2 act at z_c
__device__ float g_s2 [BSZ * H_];     // decoder L2 mask
__device__ float g_U1 [MNB * H_];     // masked tangent L1 (4096,1024)
__device__ float g_G  [MNB * H_];     // h2c[b] + masked tangent L2 (4096,1024)
__device__ float g_rowloss[MNB];
__device__ float g_rowdist[MNB];

// ---------------- generic fp32 SGEMM, 128x128x8 tiles, fused epilogues ------
// EPI 0: C = relu(A@B + bias)
// EPI 2: C = relu(A@B + bias), also store float mask (pre-act > 0)
// EPI 3: C = (A@B) * mask[row>>5]
// EPI 4: C = (A@B) * mask[row>>5] + addv[row>>5]
// EPI 5: loss epilogue: v = A@B + bias; r = xnn - v; accumulate r^2 per row;
//        also (xc[row>>5] - xnn)^2 per row (for the binary kernel weight).
template<int EPI>
__global__ __launch_bounds__(256)
void sgemm_k(int M, int N, int K,
             const float* __restrict__ A, const float* __restrict__ B,
             float* __restrict__ C,
             const float* __restrict__ bias,
             const float* __restrict__ mask,
             const float* __restrict__ addv,
             float* __restrict__ smaskOut,
             const float* __restrict__ xnn,
             const float* __restrict__ xc,
             float* __restrict__ rowloss,
             float* __restrict__ rowdist)
{
    __shared__ float As[8][128];
    __shared__ float Bs[8][128];
    __shared__ float sL[128];
    __shared__ float sD[128];

    const int tid = threadIdx.x;
    const int bx = blockIdx.x, by = blockIdx.y;
    const int ty = tid >> 4, tx = tid & 15;

    const int arow = tid >> 1;            // 0..127
    const int acol = (tid & 1) << 2;      // 0 or 4
    const int brow = tid >> 5;            // 0..7
    const int bcol = (tid & 31) << 2;     // 0..124

    const float* Aptr = A + (size_t)(by * 128 + arow) * K + acol;
    const float* Bptr = B + (size_t)brow * N + bx * 128 + bcol;

    float acc[8][8];
#pragma unroll
    for (int i = 0; i < 8; i++)
#pragma unroll
        for (int j = 0; j < 8; j++) acc[i][j] = 0.f;

    for (int kt = 0; kt < K; kt += 8) {
        float4 av = *reinterpret_cast<const float4*>(Aptr + kt);
        float4 bv = *reinterpret_cast<const float4*>(Bptr + (size_t)kt * N);
        As[acol + 0][arow] = av.x;
        As[acol + 1][arow] = av.y;
        As[acol + 2][arow] = av.z;
        As[acol + 3][arow] = av.w;
        *reinterpret_cast<float4*>(&Bs[brow][bcol]) = bv;
        __syncthreads();
#pragma unroll
        for (int k = 0; k < 8; k++) {
            float4 a0 = *reinterpret_cast<const float4*>(&As[k][ty * 8]);
            float4 a1 = *reinterpret_cast<const float4*>(&As[k][ty * 8 + 4]);
            float4 b0 = *reinterpret_cast<const float4*>(&Bs[k][tx * 8]);
            float4 b1 = *reinterpret_cast<const float4*>(&Bs[k][tx * 8 + 4]);
            float ar[8] = {a0.x, a0.y, a0.z, a0.w, a1.x, a1.y, a1.z, a1.w};
            float br[8] = {b0.x, b0.y, b0.z, b0.w, b1.x, b1.y, b1.z, b1.w};
#pragma unroll
            for (int i = 0; i < 8; i++)
#pragma unroll
                for (int j = 0; j < 8; j++)
                    acc[i][j] = fmaf(ar[i], br[j], acc[i][j]);
        }
        __syncthreads();
    }

    const int rbase = by * 128 + ty * 8;
    const int cbase = bx * 128 + tx * 8;

    if constexpr (EPI == 0 || EPI == 2) {
#pragma unroll
        for (int i = 0; i < 8; i++) {
            int r = rbase + i;
#pragma unroll
            for (int j = 0; j < 8; j++) {
                int c = cbase + j;
                float v = acc[i][j] + bias[c];
                C[(size_t)r * N + c] = fmaxf(v, 0.f);
                if constexpr (EPI == 2)
                    smaskOut[(size_t)r * N + c] = v > 0.f ? 1.f : 0.f;
            }
        }
    } else if constexpr (EPI == 3) {
#pragma unroll
        for (int i = 0; i < 8; i++) {
            int r = rbase + i;
            const float* mrow = mask + (size_t)(r >> 5) * N;
#pragma unroll
            for (int j = 0; j < 8; j++) {
                int c = cbase + j;
                C[(size_t)r * N + c] = acc[i][j] * mrow[c];
            }
        }
    } else if constexpr (EPI == 4) {
#pragma unroll
        for (int i = 0; i < 8; i++) {
            int r = rbase + i;
            const float* mrow = mask + (size_t)(r >> 5) * N;
            const float* arow2 = addv + (size_t)(r >> 5) * N;
#pragma unroll
            for (int j = 0; j < 8; j++) {
                int c = cbase + j;
                C[(size_t)r * N + c] = fmaf(acc[i][j], mrow[c], arow2[c]);
            }
        }
    } else {  // EPI == 5: loss
        if (tid < 128) { sL[tid] = 0.f; sD[tid] = 0.f; }
        __syncthreads();
#pragma unroll
        for (int i = 0; i < 8; i++) {
            int r = rbase + i;
            const float* xnrow = xnn + (size_t)r * N;
            const float* xcrow = xc + (size_t)(r >> 5) * N;
            float ls = 0.f, ds = 0.f;
#pragma unroll
            for (int j = 0; j < 8; j++) {
                int c = cbase + j;
                float v = acc[i][j] + bias[c];
                float xn = xnrow[c];
                float rr = xn - v;
                ls = fmaf(rr, rr, ls);
                float dd = xcrow[c] - xn;
                ds = fmaf(dd, dd, ds);
            }
            atomicAdd(&sL[ty * 8 + i], ls);
            atomicAdd(&sD[ty * 8 + i], ds);
        }
        __syncthreads();
        if (tid < 128) {
            atomicAdd(&rowloss[by * 128 + tid], sL[tid]);
            atomicAdd(&rowdist[by * 128 + tid], sD[tid]);
        }
    }
}

// ---------------- small kernels ---------------------------------------------
__global__ void zero_k(float* a, float* b) {
    int i = blockIdx.x * blockDim.x + threadIdx.x;
    if (i < MNB) { a[i] = 0.f; b[i] = 0.f; }
}

// encoder layer 3: Z = H2 @ We3 + be3   (4224,1024)@(1024,32)
__global__ void enc3_k(const float* __restrict__ H2, const float* __restrict__ W,
                       const float* __restrict__ b, float* __restrict__ Zo) {
    int row = blockIdx.x * 8 + (threadIdx.x >> 5);
    int col = threadIdx.x & 31;
    float acc = b[col];
    const float* h = H2 + (size_t)row * H_;
#pragma unroll 8
    for (int k = 0; k < H_; k++) acc = fmaf(h[k], W[k * Z_ + col], acc);
    Zo[row * Z_ + col] = acc;
}

// dz[r,:] = Z[128+r,:] - Z[r>>5,:]
__global__ void dz_k(const float* __restrict__ Zl, float* __restrict__ dz) {
    int idx = blockIdx.x * blockDim.x + threadIdx.x;   // < 4096*32
    int r = idx >> 5, j = idx & 31;
    dz[idx] = Zl[(BSZ + r) * Z_ + j] - Zl[(r >> 5) * Z_ + j];
}

// decoder layer 1 at z_c: a1 = z_c @ Wd1 + bd1; store relu + mask
__global__ void dec1c_k(const float* __restrict__ Zl, const float* __restrict__ Wd1,
                        const float* __restrict__ bd1,
                        float* __restrict__ h1c, float* __restrict__ s1) {
    int idx = blockIdx.x * blockDim.x + threadIdx.x;   // < 128*1024
    int row = idx >> 10, col = idx & 1023;
    float acc = bd1[col];
#pragma unroll
    for (int k = 0; k < Z_; k++)
        acc = fmaf(Zl[row * Z_ + k], Wd1[k * H_ + col], acc);
    h1c[idx] = fmaxf(acc, 0.f);
    s1[idx]  = acc > 0.f ? 1.f : 0.f;
}

// final: out = mean(weight * rowloss); weight = dist>EPS ? 1 : 0.5
__global__ void reduce_k(const float* __restrict__ rl, const float* __restrict__ rd,
                         float* __restrict__ out) {
    __shared__ float s[256];
    float acc = 0.f;
    for (int i = threadIdx.x; i < MNB; i += 256) {
        float w = rd[i] > 1e-24f ? 1.0f : 0.5f;   // dist^2 > EPS^2
        acc += w * rl[i];
    }
    s[threadIdx.x] = acc;
    __syncthreads();
    for (int st = 128; st > 0; st >>= 1) {
        if (threadIdx.x < st) s[threadIdx.x] += s[threadIdx.x + st];
        __syncthreads();
    }
    if (threadIdx.x == 0) out[0] = s[0] / (float)MNB;
}

// ---------------- launch ------------------------------------------------------
extern "C" void kernel_launch(void* const* d_in, const int* in_sizes, int n_in,
                              void* d_out, int out_size) {
    const float* x_c = (const float*)d_in[0];
    const float* x_nn = (const float*)d_in[1];
    const float* We1 = (const float*)d_in[2];  const float* be1 = (const float*)d_in[3];
    const float* We2 = (const float*)d_in[4];  const float* be2 = (const float*)d_in[5];
    const float* We3 = (const float*)d_in[6];  const float* be3 = (const float*)d_in[7];
    const float* Wd1 = (const float*)d_in[8];  const float* bd1 = (const float*)d_in[9];
    const float* Wd2 = (const float*)d_in[10]; const float* bd2 = (const float*)d_in[11];
    const float* Wd3 = (const float*)d_in[12]; const float* bd3 = (const float*)d_in[13];
    float* out = (float*)d_out;

    float *pH1, *pH2, *pZ, *pdz, *ph1c, *ps1, *ph2c, *ps2, *pU1, *pG, *prl, *prd;
    cudaGetSymbolAddress((void**)&pH1, g_H1);
    cudaGetSymbolAddress((void**)&pH2, g_H2);
    cudaGetSymbolAddress((void**)&pZ, g_Zl);
    cudaGetSymbolAddress((void**)&pdz, g_dz);
    cudaGetSymbolAddress((void**)&ph1c, g_h1c);
    cudaGetSymbolAddress((void**)&ps1, g_s1);
    cudaGetSymbolAddress((void**)&ph2c, g_h2c);
    cudaGetSymbolAddress((void**)&ps2, g_s2);
    cudaGetSymbolAddress((void**)&pU1, g_U1);
    cudaGetSymbolAddress((void**)&pG, g_G);
    cudaGetSymbolAddress((void**)&prl, g_rowloss);
    cudaGetSymbolAddress((void**)&prd, g_rowdist);

    // zero per-row accumulators (graph replays rerun this)
    zero_k<<<16, 256>>>(prl, prd);

    // encoder L1: relu(X @ We1 + be1) for x_c (rows 0..127) and x_nn (rows 128..4223)
    sgemm_k<0><<<dim3(H_ / 128, BSZ / 128), 256>>>(BSZ, H_, D_, x_c, We1, pH1, be1,
        nullptr, nullptr, nullptr, nullptr, nullptr, nullptr, nullptr);
    sgemm_k<0><<<dim3(H_ / 128, MNB / 128), 256>>>(MNB, H_, D_, x_nn, We1, pH1 + BSZ * H_, be1,
        nullptr, nullptr, nullptr, nullptr, nullptr, nullptr, nullptr);

    // encoder L2
    sgemm_k<0><<<dim3(H_ / 128, MALL / 128), 256>>>(MALL, H_, H_, pH1, We2, pH2, be2,
        nullptr, nullptr, nullptr, nullptr, nullptr, nullptr, nullptr);

    // encoder L3 (N=32 specialized)
    enc3_k<<<MALL / 8, 256>>>(pH2, We3, be3, pZ);

    // dz and decoder L1 at z_c
    dz_k<<<(MNB * Z_) / 256, 256>>>(pZ, pdz);
    dec1c_k<<<(BSZ * H_) / 256, 256>>>(pZ, Wd1, bd1, ph1c, ps1);

    // tangent L1: U1 = (dz @ Wd1) * s1[b]
    sgemm_k<3><<<dim3(H_ / 128, MNB / 128), 256>>>(MNB, H_, Z_, pdz, Wd1, pU1,
        nullptr, ps1, nullptr, nullptr, nullptr, nullptr, nullptr, nullptr);

    // decoder L2 at z_c: h2c = relu(h1c @ Wd2 + bd2), record mask s2
    sgemm_k<2><<<dim3(H_ / 128, BSZ / 128), 256>>>(BSZ, H_, H_, ph1c, Wd2, ph2c, bd2,
        nullptr, nullptr, ps2, nullptr, nullptr, nullptr, nullptr);

    // G = (U1 @ Wd2) * s2[b] + h2c[b]
    sgemm_k<4><<<dim3(H_ / 128, MNB / 128), 256>>>(MNB, H_, H_, pU1, Wd2, pG,
        nullptr, ps2, ph2c, nullptr, nullptr, nullptr, nullptr, nullptr);

    // final fused GEMM + loss: n_recon = G @ Wd3 + bd3; accumulate per-row
    // ||x_nn - n_recon||^2 and ||x_c - x_nn||^2
    sgemm_k<5><<<dim3(D_ / 128, MNB / 128), 256>>>(MNB, D_, H_, pG, Wd3, nullptr, bd3,
        nullptr, nullptr, nullptr, x_nn, x_c, prl, prd);

    // weighted mean -> scalar
    reduce_k<<<1, 256>>>(prl, prd, out);
}

// round 5
// speedup vs baseline: 8.8392x; 8.8392x over previous
#include <cuda_runtime.h>
#include <cuda_bf16.h>
#include <cstdint>

// Problem constants
#define BSZ   128
#define NN_   32
#define D_    3072
#define H_    1024
#define Z_    32
#define MALL  (BSZ + BSZ*NN_)   // 4224
#define MNB   (BSZ*NN_)         // 4096
#define KPAD  64

// ---------------- scratch (static device globals; allocation-free) ----------
__device__ __align__(128) __nv_bfloat16 g_Xall[MALL * D_];
__device__ __align__(128) __nv_bfloat16 g_We1t[H_ * D_];
__device__ __align__(128) __nv_bfloat16 g_We2t[H_ * H_];
__device__ __align__(128) __nv_bfloat16 g_Wd2t[H_ * H_];
__device__ __align__(128) __nv_bfloat16 g_Wd3t[D_ * H_];
__device__ __align__(128) __nv_bfloat16 g_We3t[128 * H_];
__device__ __align__(128) __nv_bfloat16 g_Wd1t[H_ * KPAD];
__device__ __align__(128) __nv_bfloat16 g_H1[MALL * H_];
__device__ __align__(128) __nv_bfloat16 g_H2[MALL * H_];
__device__ __align__(128) float         g_Zl[MALL * Z_];
__device__ __align__(128) __nv_bfloat16 g_dzp[MNB * KPAD];
__device__ __align__(128) __nv_bfloat16 g_h1c[BSZ * H_];
__device__ __align__(128) float         g_s1 [BSZ * H_];
__device__ __align__(128) float         g_h2c[BSZ * H_];
__device__ __align__(128) float         g_s2 [BSZ * H_];
__device__ __align__(128) __nv_bfloat16 g_U1 [MNB * H_];
__device__ __align__(128) __nv_bfloat16 g_G  [MNB * H_];
__device__ float g_rowloss[MNB];
__device__ float g_rowdist[MNB];

// ---------------- PTX helpers (all baseline sm_80-class, no 'a' features) ---
__device__ __forceinline__ uint32_t s2u(const void* p) {
    uint32_t a;
    asm("{ .reg .u64 t; cvta.to.shared.u64 t, %1; cvt.u32.u64 %0, t; }" : "=r"(a) : "l"(p));
    return a;
}
__device__ __forceinline__ void cpa16(uint32_t d, const void* g) {
    asm volatile("cp.async.cg.shared.global [%0], [%1], 16;" :: "r"(d), "l"(g) : "memory");
}
__device__ __forceinline__ void cpa_commit() {
    asm volatile("cp.async.commit_group;" ::: "memory");
}
template<int NWAIT> __device__ __forceinline__ void cpa_wait() {
    asm volatile("cp.async.wait_group %0;" :: "n"(NWAIT) : "memory");
}
__device__ __forceinline__ void ldsm4(uint32_t& r0, uint32_t& r1, uint32_t& r2, uint32_t& r3,
                                      uint32_t a) {
    asm volatile("ldmatrix.sync.aligned.m8n8.x4.shared.b16 {%0,%1,%2,%3}, [%4];"
                 : "=r"(r0), "=r"(r1), "=r"(r2), "=r"(r3) : "r"(a));
}
__device__ __forceinline__ void ldsm2(uint32_t& r0, uint32_t& r1, uint32_t a) {
    asm volatile("ldmatrix.sync.aligned.m8n8.x2.shared.b16 {%0,%1}, [%2];"
                 : "=r"(r0), "=r"(r1) : "r"(a));
}
__device__ __forceinline__ void mma16816(float* c, const uint32_t* a, const uint32_t* b) {
    asm volatile(
        "mma.sync.aligned.m16n8k16.row.col.f32.bf16.bf16.f32 "
        "{%0,%1,%2,%3}, {%4,%5,%6,%7}, {%8,%9}, {%0,%1,%2,%3};"
        : "+f"(c[0]), "+f"(c[1]), "+f"(c[2]), "+f"(c[3])
        : "r"(a[0]), "r"(a[1]), "r"(a[2]), "r"(a[3]), "r"(b[0]), "r"(b[1]));
}
#define SWZ(x) ((x) ^ ((((uint32_t)(x)) >> 3) & 0x70))

// ---------------- tensor-core GEMM: D = A(M,K) @ B(N,K)^T ------------------
// CTA tile 128x128, K-step 64. 8 warps: wm = wid>>2 (2 x 64 rows), wn = wid&3
// (4 x 32 cols). Per warp 4x4 m16n8k16 tiles.
// EPI 0 RELU bf16 out | 1 MUL bf16 | 2 relu+mask fp32x2 | 3 MADD bf16
// EPI 4 Z fp32 (cols 0..31, ldc=32) | 5 LOSS rowwise
template<int EPI>
__global__ __launch_bounds__(256)
void tcgemm(const __nv_bfloat16* __restrict__ A, const __nv_bfloat16* __restrict__ B,
            int K, int ldc,
            const float* __restrict__ bias, const float* __restrict__ mask,
            const float* __restrict__ addv,
            __nv_bfloat16* __restrict__ outb, float* __restrict__ outf,
            float* __restrict__ outf2,
            const float* __restrict__ xnn, float* __restrict__ rowloss)
{
    extern __shared__ char smem[];
    const uint32_t sb = s2u(smem);
    const int tid = threadIdx.x, wid = tid >> 5, lid = tid & 31;
    const int wm = wid >> 2, wn = wid & 3;
    const int bx = blockIdx.x, by = blockIdx.y;
    const int nk = K >> 6;

    float acc[4][4][4];
#pragma unroll
    for (int i = 0; i < 4; i++)
#pragma unroll
        for (int j = 0; j < 4; j++)
#pragma unroll
            for (int q = 0; q < 4; q++) acc[i][j][q] = 0.f;

    auto loadtile = [&](int kt, int s) {
        const uint32_t ao = (uint32_t)s * 16384u;
        const uint32_t bo = 32768u + (uint32_t)s * 16384u;
        const char* Ag = (const char*)(A + (size_t)(by * 128) * K + kt * 64);
        const char* Bg = (const char*)(B + (size_t)(bx * 128) * K + kt * 64);
        const size_t stride = (size_t)K * 2;
#pragma unroll
        for (int i = 0; i < 4; i++) {
            int cid = tid + i * 256;
            int r = cid >> 3;
            int co = (cid & 7) * 16;
            cpa16(sb + ao + SWZ(r * 128 + co), Ag + (size_t)r * stride + co);
            cpa16(sb + bo + SWZ(r * 128 + co), Bg + (size_t)r * stride + co);
        }
    };

    loadtile(0, 0); cpa_commit();
    if (nk > 1) { loadtile(1, 1); cpa_commit(); }

    for (int kt = 0; kt < nk; kt++) {
        const int s = kt & 1;
        if (kt + 1 < nk) cpa_wait<1>(); else cpa_wait<0>();
        __syncthreads();
        const uint32_t abase = sb + (uint32_t)s * 16384u;
        const uint32_t bbase = sb + 32768u + (uint32_t)s * 16384u;
#pragma unroll
        for (int ks = 0; ks < 4; ks++) {
            uint32_t af[4][4], bf_[4][2];
            // A frags: ldmatrix lane l -> matrix l/8, row l%8
            const int arowL = ((lid >> 3) & 1) * 8 + (lid & 7);
            const int acolL = ks * 32 + (lid >> 4) * 16;
#pragma unroll
            for (int mt = 0; mt < 4; mt++) {
                int row = wm * 64 + mt * 16 + arowL;
                ldsm4(af[mt][0], af[mt][1], af[mt][2], af[mt][3],
                      abase + SWZ(row * 128 + acolL));
            }
            const int browL = lid & 7;
            const int bcolL = ks * 32 + ((lid >> 3) & 1) * 16;
#pragma unroll
            for (int nt = 0; nt < 4; nt++) {
                int nrow = wn * 32 + nt * 8 + browL;
                ldsm2(bf_[nt][0], bf_[nt][1], bbase + SWZ(nrow * 128 + bcolL));
            }
#pragma unroll
            for (int mt = 0; mt < 4; mt++)
#pragma unroll
                for (int nt = 0; nt < 4; nt++)
                    mma16816(acc[mt][nt], af[mt], bf_[nt]);
        }
        __syncthreads();
        if (kt + 2 < nk) { loadtile(kt + 2, s); cpa_commit(); }
    }

    // ---------------- epilogue (register accumulators) ----------------
    const int q = lid >> 2;            // 0..7
    const int cpos = (lid & 3) * 2;    // 0,2,4,6

    if constexpr (EPI == 5) {
        __syncthreads();
        float* sL = (float*)smem;
        if (tid < 128) sL[tid] = 0.f;
        __syncthreads();
#pragma unroll
        for (int mt = 0; mt < 4; mt++) {
            const int r0l = wm * 64 + mt * 16 + q;
            const int R0 = by * 128 + r0l;
            float lsA = 0.f, lsB = 0.f;
#pragma unroll
            for (int nt = 0; nt < 4; nt++) {
                const int C = bx * 128 + wn * 32 + nt * 8 + cpos;
                float2 bb = *(const float2*)(bias + C);
                float2 x0 = *(const float2*)(xnn + (size_t)R0 * D_ + C);
                float2 x1 = *(const float2*)(xnn + (size_t)(R0 + 8) * D_ + C);
                float r;
                r = x0.x - (acc[mt][nt][0] + bb.x); lsA = fmaf(r, r, lsA);
                r = x0.y - (acc[mt][nt][1] + bb.y); lsA = fmaf(r, r, lsA);
                r = x1.x - (acc[mt][nt][2] + bb.x); lsB = fmaf(r, r, lsB);
                r = x1.y - (acc[mt][nt][3] + bb.y); lsB = fmaf(r, r, lsB);
            }
            lsA += __shfl_xor_sync(0xffffffffu, lsA, 1);
            lsA += __shfl_xor_sync(0xffffffffu, lsA, 2);
            lsB += __shfl_xor_sync(0xffffffffu, lsB, 1);
            lsB += __shfl_xor_sync(0xffffffffu, lsB, 2);
            if ((lid & 3) == 0) {
                atomicAdd(&sL[r0l], lsA);
                atomicAdd(&sL[r0l + 8], lsB);
            }
        }
        __syncthreads();
        if (tid < 128) atomicAdd(&rowloss[by * 128 + tid], sL[tid]);
        return;
    }

#pragma unroll
    for (int mt = 0; mt < 4; mt++) {
        const int R0 = by * 128 + wm * 64 + mt * 16 + q;
        const int R1 = R0 + 8;
#pragma unroll
        for (int nt = 0; nt < 4; nt++) {
            const int Cl = wn * 32 + nt * 8 + cpos;
            const int C = bx * 128 + Cl;
            float v0 = acc[mt][nt][0], v1 = acc[mt][nt][1];
            float v2 = acc[mt][nt][2], v3 = acc[mt][nt][3];
            if constexpr (EPI == 0) {
                float2 bb = *(const float2*)(bias + C);
                v0 = fmaxf(v0 + bb.x, 0.f); v1 = fmaxf(v1 + bb.y, 0.f);
                v2 = fmaxf(v2 + bb.x, 0.f); v3 = fmaxf(v3 + bb.y, 0.f);
                __nv_bfloat162 h0, h1;
                h0.x = __float2bfloat16_rn(v0); h0.y = __float2bfloat16_rn(v1);
                h1.x = __float2bfloat16_rn(v2); h1.y = __float2bfloat16_rn(v3);
                *(__nv_bfloat162*)(outb + (size_t)R0 * ldc + C) = h0;
                *(__nv_bfloat162*)(outb + (size_t)R1 * ldc + C) = h1;
            } else if constexpr (EPI == 1) {
                float2 m0 = *(const float2*)(mask + (size_t)(R0 >> 5) * H_ + C);
                float2 m1 = *(const float2*)(mask + (size_t)(R1 >> 5) * H_ + C);
                __nv_bfloat162 h0, h1;
                h0.x = __float2bfloat16_rn(v0 * m0.x); h0.y = __float2bfloat16_rn(v1 * m0.y);
                h1.x = __float2bfloat16_rn(v2 * m1.x); h1.y = __float2bfloat16_rn(v3 * m1.y);
                *(__nv_bfloat162*)(outb + (size_t)R0 * ldc + C) = h0;
                *(__nv_bfloat162*)(outb + (size_t)R1 * ldc + C) = h1;
            } else if constexpr (EPI == 2) {
                float2 bb = *(const float2*)(bias + C);
                float a0 = v0 + bb.x, a1 = v1 + bb.y, a2 = v2 + bb.x, a3 = v3 + bb.y;
                float2 r0 = make_float2(fmaxf(a0, 0.f), fmaxf(a1, 0.f));
                float2 r1 = make_float2(fmaxf(a2, 0.f), fmaxf(a3, 0.f));
                float2 s0 = make_float2(a0 > 0.f ? 1.f : 0.f, a1 > 0.f ? 1.f : 0.f);
                float2 s1 = make_float2(a2 > 0.f ? 1.f : 0.f, a3 > 0.f ? 1.f : 0.f);
                *(float2*)(outf  + (size_t)R0 * ldc + C) = r0;
                *(float2*)(outf  + (size_t)R1 * ldc + C) = r1;
                *(float2*)(outf2 + (size_t)R0 * ldc + C) = s0;
                *(float2*)(outf2 + (size_t)R1 * ldc + C) = s1;
            } else if constexpr (EPI == 3) {
                float2 m0 = *(const float2*)(mask + (size_t)(R0 >> 5) * H_ + C);
                float2 m1 = *(const float2*)(mask + (size_t)(R1 >> 5) * H_ + C);
                float2 a0 = *(const float2*)(addv + (size_t)(R0 >> 5) * H_ + C);
                float2 a1 = *(const float2*)(addv + (size_t)(R1 >> 5) * H_ + C);
                __nv_bfloat162 h0, h1;
                h0.x = __float2bfloat16_rn(fmaf(v0, m0.x, a0.x));
                h0.y = __float2bfloat16_rn(fmaf(v1, m0.y, a0.y));
                h1.x = __float2bfloat16_rn(fmaf(v2, m1.x, a1.x));
                h1.y = __float2bfloat16_rn(fmaf(v3, m1.y, a1.y));
                *(__nv_bfloat162*)(outb + (size_t)R0 * ldc + C) = h0;
                *(__nv_bfloat162*)(outb + (size_t)R1 * ldc + C) = h1;
            } else if constexpr (EPI == 4) {
                if (wn == 0) {
                    float2 bb = *(const float2*)(bias + Cl);
                    *(float2*)(outf + (size_t)R0 * 32 + Cl) =
                        make_float2(v0 + bb.x, v1 + bb.y);
                    *(float2*)(outf + (size_t)R1 * 32 + Cl) =
                        make_float2(v2 + bb.x, v3 + bb.y);
                }
            }
        }
    }
}

// ---------------- prep / small kernels ---------------------------------------
__global__ void tconv_k(const float* __restrict__ in, __nv_bfloat16* __restrict__ out,
                        int R, int C, int Rpad) {
    __shared__ float t[32][33];
    const int k0 = blockIdx.x * 32, n0 = blockIdx.y * 32;
    const int tx = threadIdx.x, ty = threadIdx.y;
#pragma unroll
    for (int i = 0; i < 4; i++) {
        int k = k0 + ty + i * 8, n = n0 + tx;
        t[ty + i * 8][tx] = (k < R && n < C) ? in[(size_t)k * C + n] : 0.f;
    }
    __syncthreads();
#pragma unroll
    for (int i = 0; i < 4; i++) {
        int n = n0 + ty + i * 8, k = k0 + tx;
        out[(size_t)n * Rpad + k] = __float2bfloat16_rn(t[tx][ty + i * 8]);
    }
}

__global__ void cvt_k(const float* __restrict__ in, __nv_bfloat16* __restrict__ out, int n4) {
    int i = blockIdx.x * blockDim.x + threadIdx.x;
    if (i < n4) {
        float4 v = ((const float4*)in)[i];
        __nv_bfloat162 a, b;
        a.x = __float2bfloat16_rn(v.x); a.y = __float2bfloat16_rn(v.y);
        b.x = __float2bfloat16_rn(v.z); b.y = __float2bfloat16_rn(v.w);
        ((__nv_bfloat162*)out)[2 * i] = a;
        ((__nv_bfloat162*)out)[2 * i + 1] = b;
    }
}

__global__ void dist_k(const float* __restrict__ x_c, const float* __restrict__ x_nn,
                       float* __restrict__ rowdist, float* __restrict__ rowloss) {
    __shared__ float s[256];
    const int r = blockIdx.x;
    const float4* xn = (const float4*)(x_nn + (size_t)r * D_);
    const float4* xc = (const float4*)(x_c + (size_t)(r >> 5) * D_);
    float acc = 0.f;
    for (int i = threadIdx.x; i < D_ / 4; i += 256) {
        float4 a = xc[i], b = xn[i];
        float dx = a.x - b.x, dy = a.y - b.y, dz2 = a.z - b.z, dw = a.w - b.w;
        acc = fmaf(dx, dx, acc); acc = fmaf(dy, dy, acc);
        acc = fmaf(dz2, dz2, acc); acc = fmaf(dw, dw, acc);
    }
    s[threadIdx.x] = acc;
    __syncthreads();
    for (int st = 128; st > 0; st >>= 1) {
        if (threadIdx.x < st) s[threadIdx.x] += s[threadIdx.x + st];
        __syncthreads();
    }
    if (threadIdx.x == 0) { rowdist[r] = s[0]; rowloss[r] = 0.f; }
}

__global__ void dz_k(const float* __restrict__ Zl, __nv_bfloat16* __restrict__ dzp) {
    int idx = blockIdx.x * blockDim.x + threadIdx.x;
    int r = idx >> 6, j = idx & 63;
    float v = (j < Z_) ? (Zl[(BSZ + r) * Z_ + j] - Zl[(r >> 5) * Z_ + j]) : 0.f;
    dzp[idx] = __float2bfloat16_rn(v);
}

__global__ void dec1c_k(const float* __restrict__ Zl, const float* __restrict__ Wd1,
                        const float* __restrict__ bd1,
                        __nv_bfloat16* __restrict__ h1c, float* __restrict__ s1) {
    int idx = blockIdx.x * blockDim.x + threadIdx.x;
    int row = idx >> 10, col = idx & 1023;
    float acc = bd1[col];
#pragma unroll
    for (int k = 0; k < Z_; k++)
        acc = fmaf(Zl[row * Z_ + k], Wd1[k * H_ + col], acc);
    h1c[idx] = __float2bfloat16_rn(fmaxf(acc, 0.f));
    s1[idx] = acc > 0.f ? 1.f : 0.f;
}

__global__ void reduce_k(const float* __restrict__ rl, const float* __restrict__ rd,
                         float* __restrict__ out) {
    __shared__ float s[256];
    float acc = 0.f;
    for (int i = threadIdx.x; i < MNB; i += 256) {
        float w = rd[i] > 1e-24f ? 1.0f : 0.5f;
        acc += w * rl[i];
    }
    s[threadIdx.x] = acc;
    __syncthreads();
    for (int st = 128; st > 0; st >>= 1) {
        if (threadIdx.x < st) s[threadIdx.x] += s[threadIdx.x + st];
        __syncthreads();
    }
    if (threadIdx.x == 0) out[0] = s[0] / (float)MNB;
}

// ---------------- launch ------------------------------------------------------
#define TC_SMEM 65536

extern "C" void kernel_launch(void* const* d_in, const int* in_sizes, int n_in,
                              void* d_out, int out_size) {
    const float* x_c = (const float*)d_in[0];
    const float* x_nn = (const float*)d_in[1];
    const float* We1 = (const float*)d_in[2];  const float* be1 = (const float*)d_in[3];
    const float* We2 = (const float*)d_in[4];  const float* be2 = (const float*)d_in[5];
    const float* We3 = (const float*)d_in[6];  const float* be3 = (const float*)d_in[7];
    const float* Wd1 = (const float*)d_in[8];  const float* bd1 = (const float*)d_in[9];
    const float* Wd2 = (const float*)d_in[10]; const float* bd2 = (const float*)d_in[11];
    const float* Wd3 = (const float*)d_in[12]; const float* bd3 = (const float*)d_in[13];
    float* out = (float*)d_out;

    __nv_bfloat16 *pXall, *pWe1t, *pWe2t, *pWd2t, *pWd3t, *pWe3t, *pWd1t;
    __nv_bfloat16 *pH1, *pH2, *pdzp, *ph1c, *pU1, *pG;
    float *pZ, *ps1, *ph2c, *ps2, *prl, *prd;
    cudaGetSymbolAddress((void**)&pXall, g_Xall);
    cudaGetSymbolAddress((void**)&pWe1t, g_We1t);
    cudaGetSymbolAddress((void**)&pWe2t, g_We2t);
    cudaGetSymbolAddress((void**)&pWd2t, g_Wd2t);
    cudaGetSymbolAddress((void**)&pWd3t, g_Wd3t);
    cudaGetSymbolAddress((void**)&pWe3t, g_We3t);
    cudaGetSymbolAddress((void**)&pWd1t, g_Wd1t);
    cudaGetSymbolAddress((void**)&pH1, g_H1);
    cudaGetSymbolAddress((void**)&pH2, g_H2);
    cudaGetSymbolAddress((void**)&pZ, g_Zl);
    cudaGetSymbolAddress((void**)&pdzp, g_dzp);
    cudaGetSymbolAddress((void**)&ph1c, g_h1c);
    cudaGetSymbolAddress((void**)&ps1, g_s1);
    cudaGetSymbolAddress((void**)&ph2c, g_h2c);
    cudaGetSymbolAddress((void**)&ps2, g_s2);
    cudaGetSymbolAddress((void**)&pU1, g_U1);
    cudaGetSymbolAddress((void**)&pG, g_G);
    cudaGetSymbolAddress((void**)&prl, g_rowloss);
    cudaGetSymbolAddress((void**)&prd, g_rowdist);

    static bool attr_done = false;
    if (!attr_done) {
        cudaFuncSetAttribute(tcgemm<0>, cudaFuncAttributeMaxDynamicSharedMemorySize, TC_SMEM);
        cudaFuncSetAttribute(tcgemm<1>, cudaFuncAttributeMaxDynamicSharedMemorySize, TC_SMEM);
        cudaFuncSetAttribute(tcgemm<2>, cudaFuncAttributeMaxDynamicSharedMemorySize, TC_SMEM);
        cudaFuncSetAttribute(tcgemm<3>, cudaFuncAttributeMaxDynamicSharedMemorySize, TC_SMEM);
        cudaFuncSetAttribute(tcgemm<4>, cudaFuncAttributeMaxDynamicSharedMemorySize, TC_SMEM);
        cudaFuncSetAttribute(tcgemm<5>, cudaFuncAttributeMaxDynamicSharedMemorySize, TC_SMEM);
        attr_done = true;
    }

    // prep: distances (+ zero rowloss), bf16 converts, weight transposes
    dist_k<<<MNB, 256>>>(x_c, x_nn, prd, prl);
    {
        int n4 = BSZ * D_ / 4;
        cvt_k<<<(n4 + 255) / 256, 256>>>(x_c, pXall, n4);
        int m4 = MNB * D_ / 4;
        cvt_k<<<(m4 + 255) / 256, 256>>>(x_nn, pXall + (size_t)BSZ * D_, m4);
    }
    dim3 tb(32, 8);
    tconv_k<<<dim3(D_ / 32, H_ / 32), tb>>>(We1, pWe1t, D_, H_, D_);
    tconv_k<<<dim3(H_ / 32, H_ / 32), tb>>>(We2, pWe2t, H_, H_, H_);
    tconv_k<<<dim3(H_ / 32, H_ / 32), tb>>>(Wd2, pWd2t, H_, H_, H_);
    tconv_k<<<dim3(H_ / 32, D_ / 32), tb>>>(Wd3, pWd3t, H_, D_, H_);
    tconv_k<<<dim3(H_ / 32, 128 / 32), tb>>>(We3, pWe3t, H_, Z_, H_);
    tconv_k<<<dim3(KPAD / 32, H_ / 32), tb>>>(Wd1, pWd1t, Z_, H_, KPAD);

    // encoder L1: H1 = relu(Xall @ We1t^T + be1)
    tcgemm<0><<<dim3(H_ / 128, MALL / 128), 256, TC_SMEM>>>(
        pXall, pWe1t, D_, H_, be1, nullptr, nullptr, pH1, nullptr, nullptr, nullptr, nullptr);
    // encoder L2
    tcgemm<0><<<dim3(H_ / 128, MALL / 128), 256, TC_SMEM>>>(
        pH1, pWe2t, H_, H_, be2, nullptr, nullptr, pH2, nullptr, nullptr, nullptr, nullptr);
    // encoder L3 -> Z (fp32, cols 0..31)
    tcgemm<4><<<dim3(1, MALL / 128), 256, TC_SMEM>>>(
        pH2, pWe3t, H_, 32, be3, nullptr, nullptr, nullptr, pZ, nullptr, nullptr, nullptr);

    // dz (padded bf16) and decoder L1 at z_c
    dz_k<<<(MNB * KPAD) / 256, 256>>>(pZ, pdzp);
    dec1c_k<<<(BSZ * H_) / 256, 256>>>(pZ, Wd1, bd1, ph1c, ps1);

    // tangent L1: U1 = (dzp @ Wd1t^T) * s1[b]
    tcgemm<1><<<dim3(H_ / 128, MNB / 128), 256, TC_SMEM>>>(
        pdzp, pWd1t, KPAD, H_, nullptr, ps1, nullptr, pU1, nullptr, nullptr, nullptr, nullptr);
    // decoder L2 at z_c: h2c fp32 + mask s2
    tcgemm<2><<<dim3(H_ / 128, 1), 256, TC_SMEM>>>(
        ph1c, pWd2t, H_, H_, bd2, nullptr, nullptr, nullptr, ph2c, ps2, nullptr, nullptr);
    // G = (U1 @ Wd2t^T) * s2[b] + h2c[b]
    tcgemm<3><<<dim3(H_ / 128, MNB / 128), 256, TC_SMEM>>>(
        pU1, pWd2t, H_, H_, nullptr, ps2, ph2c, pG, nullptr, nullptr, nullptr, nullptr);
    // final fused GEMM + loss
    tcgemm<5><<<dim3(D_ / 128, MNB / 128), 256, TC_SMEM>>>(
        pG, pWd3t, H_, D_, bd3, nullptr, nullptr, nullptr, nullptr, nullptr, x_nn, prl);

    reduce_k<<<1, 256>>>(prl, prd, out);
}